// round 1
// baseline (speedup 1.0000x reference)
#include <cuda_runtime.h>
#include <math.h>

// Problem constants (from reference): B=4, C=8, H=W=512
// pads: ph = pw = (int(sqrt(2)*512) - 512)//2 + 1 = (724-512)//2 + 1 = 107
// padded: Hp = Wp = 512 + 214 = 726
#define BB 4
#define CC 8
#define HH 512
#define WW 512
#define PAD 107
#define HP 726
#define PLANE (HH * WW)            // 262144
#define DEG2RAD 0.017453292519943295f

__global__ __launch_bounds__(256)
void diff_pair_rotate_kernel(const float* __restrict__ xin,
                             const float* __restrict__ yin,
                             const float* __restrict__ angles,
                             float* __restrict__ out)
{
    const int pix = blockIdx.x * blockDim.x + threadIdx.x;   // 0 .. 512*512-1
    const int b   = blockIdx.y;
    const int oy  = pix >> 9;        // /512
    const int ox  = pix & 511;       // %512

    // Per-batch rotation (broadcast load; cheap per thread)
    const float rad = angles[b] * DEG2RAD;
    float sn, cs;
    sincosf(rad, &sn, &cs);

    // Normalized coords of this output pixel in the PADDED frame.
    // linspace(-1, 1, 726): step = 2/725
    const float step = 2.0f / 725.0f;
    const float pyv = fmaf((float)(oy + PAD), step, -1.0f);
    const float pxv = fmaf((float)(ox + PAD), step, -1.0f);

    // Rotate
    const float gx = pxv * cs - pyv * sn;
    const float gy = pxv * sn + pyv * cs;

    // Unnormalize (align_corners=False): ix = ((g+1)*Wp - 1) * 0.5
    const float ix = ((gx + 1.0f) * (float)HP - 1.0f) * 0.5f;
    const float iy = ((gy + 1.0f) * (float)HP - 1.0f) * 0.5f;

    const float x0f = floorf(ix);
    const float y0f = floorf(iy);
    const float wx1 = ix - x0f, wx0 = 1.0f - wx1;
    const float wy1 = iy - y0f, wy0 = 1.0f - wy1;

    // Convert padded integer coords -> unpadded source coords.
    // Anything landing in the pad band or outside is zero (zero padding +
    // padding_mode='zeros' coincide), so a single unsigned bounds check works.
    const int xs0 = (int)x0f - PAD;
    const int ys0 = (int)y0f - PAD;
    const int xs1 = xs0 + 1;
    const int ys1 = ys0 + 1;

    const bool vx0 = ((unsigned)xs0) < (unsigned)WW;
    const bool vx1 = ((unsigned)xs1) < (unsigned)WW;
    const bool vy0 = ((unsigned)ys0) < (unsigned)HH;
    const bool vy1 = ((unsigned)ys1) < (unsigned)HH;

    const bool v00 = vx0 & vy0;
    const bool v10 = vx1 & vy0;
    const bool v01 = vx0 & vy1;
    const bool v11 = vx1 & vy1;

    const float w00 = wx0 * wy0;
    const float w10 = wx1 * wy0;
    const float w01 = wx0 * wy1;
    const float w11 = wx1 * wy1;

    // Tap offsets within one channel plane (only dereferenced when valid).
    const int i00 = ys0 * WW + xs0;
    const int i10 = i00 + 1;
    const int i01 = i00 + WW;
    const int i11 = i01 + 1;

    const int   cstride = PLANE;
    const float* xb = xin + (size_t)(b * CC) * PLANE;
    const float* yb = yin + (size_t)(b * CC) * PLANE;
    const int   obase = (b * CC) * PLANE + oy * WW + ox;
    float* __restrict__ outx = out + obase;
    float* __restrict__ outy = out + (size_t)(BB * CC) * PLANE + obase;

#pragma unroll 4
    for (int c = 0; c < CC; ++c) {
        const float* xp = xb + c * cstride;
        const float* yp = yb + c * cstride;

        float accx = 0.0f;
        float accy = 0.0f;
        if (v00) { accx = fmaf(__ldg(xp + i00), w00, accx);
                   accy = fmaf(__ldg(yp + i00), w00, accy); }
        if (v10) { accx = fmaf(__ldg(xp + i10), w10, accx);
                   accy = fmaf(__ldg(yp + i10), w10, accy); }
        if (v01) { accx = fmaf(__ldg(xp + i01), w01, accx);
                   accy = fmaf(__ldg(yp + i01), w01, accy); }
        if (v11) { accx = fmaf(__ldg(xp + i11), w11, accx);
                   accy = fmaf(__ldg(yp + i11), w11, accy); }

        outx[c * cstride] = accx;
        outy[c * cstride] = accy;
    }
}

extern "C" void kernel_launch(void* const* d_in, const int* in_sizes, int n_in,
                              void* d_out, int out_size)
{
    const float* x      = (const float*)d_in[0];
    const float* y      = (const float*)d_in[1];
    const float* angles = (const float*)d_in[2];
    float* out          = (float*)d_out;

    dim3 block(256);
    dim3 grid((HH * WW) / 256, BB);   // 1024 x 4
    diff_pair_rotate_kernel<<<grid, block>>>(x, y, angles, out);
}